// round 2
// baseline (speedup 1.0000x reference)
#include <cuda_runtime.h>

// Shapes (fixed by the problem)
#define BB   32
#define TT   4096
#define DD   512
#define GG   8
#define OO   512
#define CHUNK 128            // tokens per main-kernel CTA
#define NCHUNK (TT/CHUNK)    // 32

// Scratch (no allocations allowed -> __device__ globals)
__device__ float d_sums[BB*GG*DD];
__device__ int   d_counts[BB*GG];
__device__ int   d_sorted_t[TT];
__device__ int   d_sorted_g[TT];

// ---------------------------------------------------------------- zero sums
__global__ void k_zero() {
    int i = blockIdx.x * blockDim.x + threadIdx.x;
    if (i < BB*GG*DD) d_sums[i] = 0.0f;
}

// ------------------------------------------------- bucket tokens by group id
// token_types is shared across batch; one small CTA builds group-contiguous
// index lists (order within a group is irrelevant up to fp rounding).
__global__ void k_sort(const int* __restrict__ tt) {
    __shared__ int hist[GG];
    __shared__ int cur[GG];
    int tid = threadIdx.x;
    if (tid < GG) hist[tid] = 0;
    __syncthreads();
    for (int t = tid; t < TT; t += blockDim.x)
        atomicAdd(&hist[tt[t]], 1);
    __syncthreads();
    if (tid == 0) {
        int s = 0;
        for (int g = 0; g < GG; g++) { cur[g] = s; s += hist[g]; }
    }
    __syncthreads();
    for (int t = tid; t < TT; t += blockDim.x) {
        int g = tt[t];
        int p = atomicAdd(&cur[g], 1);
        d_sorted_t[p] = t;
        d_sorted_g[p] = g;
    }
}

// -------------------------------------------------- per-(b,g) valid counts
// Mask is transported as int32 (bool -> int32 by the harness).
__global__ void k_count(const int* __restrict__ tt,
                        const int* __restrict__ pad) {
    __shared__ int cnt[GG];
    int b = blockIdx.x;
    int tid = threadIdx.x;
    if (tid < GG) cnt[tid] = 0;
    __syncthreads();
    const int* p = pad + (size_t)b * TT;
    for (int t = tid; t < TT; t += blockDim.x)
        if (!p[t]) atomicAdd(&cnt[tt[t]], 1);
    __syncthreads();
    if (tid < GG) d_counts[b*GG + tid] = cnt[tid];
}

// ------------------------------------------------------------- masked sums
// grid (NCHUNK, B), 128 threads: thread = one float4 lane of D=512.
// Sorted order -> single accumulator, flush at group boundaries only.
// Padded tokens skip the global load (uniform branch) -> halves HBM traffic.
__global__ void __launch_bounds__(128) k_main(const float* __restrict__ batch,
                                              const int* __restrict__ pad) {
    __shared__ int s_t[CHUNK];
    __shared__ int s_g[CHUNK];
    __shared__ int s_v[CHUNK];

    int b   = blockIdx.y;
    int c0  = blockIdx.x * CHUNK;
    int tid = threadIdx.x;

    {   // preload token meta for this chunk (CHUNK == blockDim)
        int t = d_sorted_t[c0 + tid];
        s_t[tid] = t;
        s_g[tid] = d_sorted_g[c0 + tid];
        s_v[tid] = pad[(size_t)b*TT + t] ? 0 : 1;   // int32 mask, True = padded
    }
    __syncthreads();

    const float4* bb = (const float4*)(batch + (size_t)b * TT * DD);
    float4 acc = make_float4(0.f, 0.f, 0.f, 0.f);
    int curg = s_g[0];

    for (int i = 0; i < CHUNK; i++) {
        int g = s_g[i];
        if (g != curg) {                       // uniform, rare (<=7 per chunk)
            float* dst = &d_sums[((size_t)b*GG + curg)*DD + tid*4];
            atomicAdd(dst+0, acc.x); atomicAdd(dst+1, acc.y);
            atomicAdd(dst+2, acc.z); atomicAdd(dst+3, acc.w);
            acc = make_float4(0.f, 0.f, 0.f, 0.f);
            curg = g;
        }
        if (s_v[i]) {                          // uniform: skip padded rows
            float4 v = bb[(size_t)s_t[i] * (DD/4) + tid];
            acc.x += v.x; acc.y += v.y; acc.z += v.z; acc.w += v.w;
        }
    }
    float* dst = &d_sums[((size_t)b*GG + curg)*DD + tid*4];
    atomicAdd(dst+0, acc.x); atomicAdd(dst+1, acc.y);
    atomicAdd(dst+2, acc.z); atomicAdd(dst+3, acc.w);
}

// ------------------------------------------------------ means -> GEMM + bias
// grid (G, OUT/OCH, B/BH), 128 threads. Each thread computes 2 b x 4 o.
// Means computed on smem load (divide by count, zero for empty groups).
#define BH  16     // batch rows per CTA
#define OCH 64     // outputs per CTA
#define DT  32     // d tile
#define MSTR (DD+1) // smem stride 513 -> conflict-free per-b reads

__global__ void __launch_bounds__(128) k_gemm(const float* __restrict__ W,
                                              const float* __restrict__ bias,
                                              float* __restrict__ out) {
    __shared__ float s_mean[BH * MSTR];   // 16*513*4 = 32832 B
    __shared__ float s_w[DT * OCH];       // 32*64*4  =  8192 B

    int g   = blockIdx.x;
    int o0  = blockIdx.y * OCH;
    int b0  = blockIdx.z * BH;
    int tid = threadIdx.x;

    // load means for this (g, b-slab): BH*DD floats, 64 per thread
    for (int idx = tid; idx < BH*DD; idx += 128) {
        int bl = idx >> 9;          // /512
        int d  = idx & (DD-1);
        int bg = (b0 + bl)*GG + g;
        int c  = d_counts[bg];
        float s = d_sums[(size_t)bg*DD + d];
        s_mean[bl*MSTR + d] = (c > 0) ? s / (float)c : 0.0f;
    }

    int oq = tid & 15;          // 16 quads -> 64 outputs
    int bq = tid >> 4;          // 8 pairs  -> 16 batch rows
    float a0x=0,a0y=0,a0z=0,a0w=0;
    float a1x=0,a1y=0,a1z=0,a1w=0;

    for (int d0 = 0; d0 < DD; d0 += DT) {
        __syncthreads();   // means ready (1st iter) + previous tile consumed
        // W tile: DT x OCH = 512 float4, 4 per thread, coalesced rows
        #pragma unroll
        for (int k = 0; k < 4; k++) {
            int idx = tid + k*128;
            int dd = idx >> 4;
            int o4 = idx & 15;
            const float4* wp =
                (const float4*)(W + ((size_t)(g*DD + d0 + dd))*OO + o0) + o4;
            ((float4*)s_w)[idx] = *wp;
        }
        __syncthreads();

        const float* m0 = &s_mean[(bq*2 + 0)*MSTR + d0];
        const float* m1 = &s_mean[(bq*2 + 1)*MSTR + d0];
        #pragma unroll
        for (int dd = 0; dd < DT; dd++) {
            float4 w = ((const float4*)s_w)[dd*16 + oq];
            float ma = m0[dd];
            float mb = m1[dd];
            a0x += ma*w.x; a0y += ma*w.y; a0z += ma*w.z; a0w += ma*w.w;
            a1x += mb*w.x; a1y += mb*w.y; a1z += mb*w.z; a1w += mb*w.w;
        }
    }

    int o = o0 + oq*4;
    const float* bp = bias + (size_t)g*OO + o;
    float bx = bp[0], by = bp[1], bz = bp[2], bw = bp[3];

    int b_a = b0 + bq*2 + 0;
    int b_b = b0 + bq*2 + 1;
    float* opa = out + ((size_t)(b_a*GG + g))*OO + o;
    float* opb = out + ((size_t)(b_b*GG + g))*OO + o;
    opa[0]=a0x+bx; opa[1]=a0y+by; opa[2]=a0z+bz; opa[3]=a0w+bw;
    opb[0]=a1x+bx; opb[1]=a1y+by; opb[2]=a1z+bz; opb[3]=a1w+bw;
}

// ---------------------------------------------------------------- launcher
// metadata order: batch(f32), W(f32), b_bias(f32), token_types(i32),
//                 key_padding_mask(bool -> int32)
extern "C" void kernel_launch(void* const* d_in, const int* in_sizes, int n_in,
                              void* d_out, int out_size) {
    const float* batch = (const float*)d_in[0];
    const float* W     = (const float*)d_in[1];
    const float* bias  = (const float*)d_in[2];
    const int*   tt    = (const int*)d_in[3];
    const int*   pad   = (const int*)d_in[4];
    float* out = (float*)d_out;

    k_zero<<<(BB*GG*DD + 255)/256, 256>>>();
    k_sort<<<1, 256>>>(tt);
    k_count<<<BB, 256>>>(tt, pad);

    dim3 gmain(NCHUNK, BB);
    k_main<<<gmain, 128>>>(batch, pad);

    dim3 ggemm(GG, OO/OCH, BB/BH);
    k_gemm<<<ggemm, 128>>>(W, bias, out);
}

// round 3
// speedup vs baseline: 1.6403x; 1.6403x over previous
#include <cuda_runtime.h>

#define BB   32
#define TT   4096
#define DD   512
#define GG   8
#define OO   512
#define CHUNK 128            // valid tokens per main-kernel CTA

// Scratch (__device__ globals; no allocations allowed)
__device__ float d_sums[BB*GG*DD];
__device__ int   d_counts[BB*GG];
__device__ int   d_vt[BB*TT];    // per-b valid token indices, group-sorted
__device__ int   d_vg[BB*TT];    // group id per valid slot
__device__ int   d_vcnt[BB];     // valid count per b

// ---------------------------------------------------------------- setup
// One CTA per batch row: zero sums, count valid per group, build a
// group-contiguous compacted list of valid token indices.
__global__ void __launch_bounds__(256) k_setup(const int* __restrict__ tt,
                                               const int* __restrict__ pad) {
    __shared__ int hist[GG];
    __shared__ int cur[GG];
    int b = blockIdx.x;
    int tid = threadIdx.x;

    // zero this b's sums slice: GG*DD = 4096 floats = 1024 float4
    float4* sz = (float4*)&d_sums[(size_t)b*GG*DD];
    #pragma unroll
    for (int k = 0; k < 4; k++) sz[tid + k*256] = make_float4(0.f,0.f,0.f,0.f);

    if (tid < GG) hist[tid] = 0;
    __syncthreads();

    const int* p = pad + (size_t)b*TT;   // bool -> int32 transport
    for (int t = tid; t < TT; t += 256)
        if (!p[t]) atomicAdd(&hist[tt[t]], 1);
    __syncthreads();

    if (tid == 0) {
        int s = 0;
        for (int g = 0; g < GG; g++) { cur[g] = s; s += hist[g]; }
        d_vcnt[b] = s;
    }
    if (tid < GG) d_counts[b*GG + tid] = hist[tid];
    __syncthreads();

    for (int t = tid; t < TT; t += 256) {
        if (!p[t]) {
            int g = tt[t];
            int pos = atomicAdd(&cur[g], 1);
            d_vt[b*TT + pos] = t;
            d_vg[b*TT + pos] = g;
        }
    }
}

// ------------------------------------------------------------- masked sums
// grid (TT/CHUNK, B), 256 threads. lane = tid&127 is one float4 of D=512,
// half = tid>>7 strides tokens by 2. All tokens in the list are valid ->
// branch-free 8-wide load batching (MLP 8). Group-sorted order -> per-thread
// accumulator flushed to d_sums via atomicAdd only at group boundaries.
__device__ __forceinline__ void flush_acc(int b, int g, int lane, float4 a) {
    float* dst = &d_sums[((size_t)b*GG + g)*DD + lane*4];
    atomicAdd(dst+0, a.x); atomicAdd(dst+1, a.y);
    atomicAdd(dst+2, a.z); atomicAdd(dst+3, a.w);
}

__global__ void __launch_bounds__(256) k_main(const float* __restrict__ batch) {
    __shared__ int s_tok[CHUNK];
    __shared__ int s_grp[CHUNK];

    int b   = blockIdx.y;
    int cnt = d_vcnt[b];
    int c0  = blockIdx.x * CHUNK;
    if (c0 >= cnt) return;
    int n   = min(CHUNK, cnt - c0);
    int tid = threadIdx.x;

    if (tid < n) {
        s_tok[tid] = d_vt[b*TT + c0 + tid];
        s_grp[tid] = d_vg[b*TT + c0 + tid];
    }
    __syncthreads();

    int lane = tid & 127;
    int half = tid >> 7;
    const float4* bb = (const float4*)(batch + (size_t)b * TT * DD);

    float4 acc = make_float4(0.f,0.f,0.f,0.f);
    int curg = -1;
    int i = half;

    #define ACCSTEP(J, V)                                                  \
        { int g_ = s_grp[i + 2*(J)];                                       \
          if (g_ != curg) {                                                \
              if (curg >= 0) flush_acc(b, curg, lane, acc);                \
              acc = make_float4(0.f,0.f,0.f,0.f); curg = g_; }             \
          acc.x += (V).x; acc.y += (V).y; acc.z += (V).z; acc.w += (V).w; }

    // 8 tokens per macro-step (stride 2 within half): loads batched first
    for (; i + 14 < n; i += 16) {
        float4 v0 = __ldcs(&bb[(size_t)s_tok[i     ] * (DD/4) + lane]);
        float4 v1 = __ldcs(&bb[(size_t)s_tok[i +  2] * (DD/4) + lane]);
        float4 v2 = __ldcs(&bb[(size_t)s_tok[i +  4] * (DD/4) + lane]);
        float4 v3 = __ldcs(&bb[(size_t)s_tok[i +  6] * (DD/4) + lane]);
        float4 v4 = __ldcs(&bb[(size_t)s_tok[i +  8] * (DD/4) + lane]);
        float4 v5 = __ldcs(&bb[(size_t)s_tok[i + 10] * (DD/4) + lane]);
        float4 v6 = __ldcs(&bb[(size_t)s_tok[i + 12] * (DD/4) + lane]);
        float4 v7 = __ldcs(&bb[(size_t)s_tok[i + 14] * (DD/4) + lane]);
        ACCSTEP(0, v0); ACCSTEP(1, v1); ACCSTEP(2, v2); ACCSTEP(3, v3);
        ACCSTEP(4, v4); ACCSTEP(5, v5); ACCSTEP(6, v6); ACCSTEP(7, v7);
    }
    for (; i < n; i += 2) {
        float4 v = __ldcs(&bb[(size_t)s_tok[i] * (DD/4) + lane]);
        ACCSTEP(0, v);
    }
    if (curg >= 0) flush_acc(b, curg, lane, acc);
    #undef ACCSTEP
}

// ------------------------------------------------------ means -> GEMM + bias
// grid (G, OO/128, BB/8), 256 threads. Tile: 8 b-rows x 128 outputs.
// Thread = 1 b-row x 4 outputs; mean reads are warp-broadcast (tid>>5 uniform
// within a warp). W is 8MB and L2-resident across its 4x reuse.
#define GBH  8
#define GOCH 128
#define GDT  16

__global__ void __launch_bounds__(256) k_gemm(const float* __restrict__ W,
                                              const float* __restrict__ bias,
                                              float* __restrict__ out) {
    __shared__ float s_mean[GBH * DD];      // 16 KB
    __shared__ float s_w[GDT * GOCH];       //  8 KB

    int g   = blockIdx.x;
    int o0  = blockIdx.y * GOCH;
    int b0  = blockIdx.z * GBH;
    int tid = threadIdx.x;

    // means for this (g, b-slab): 8*512 floats, divide-by-count on load
    for (int idx = tid; idx < GBH*DD; idx += 256) {
        int bl = idx >> 9;
        int d  = idx & (DD-1);
        int bg = (b0 + bl)*GG + g;
        int c  = d_counts[bg];
        float s = d_sums[(size_t)bg*DD + d];
        s_mean[bl*DD + d] = (c > 0) ? s / (float)c : 0.0f;
    }

    int oq   = tid & 31;    // 32 quads -> 128 outputs
    int brow = tid >> 5;    // 8 batch rows
    float a0=0.f, a1=0.f, a2=0.f, a3=0.f;

    for (int d0 = 0; d0 < DD; d0 += GDT) {
        __syncthreads();    // means ready (iter 0) / prev tile consumed
        // W tile: GDT x GOCH = 512 float4, 2 per thread, coalesced
        #pragma unroll
        for (int k = 0; k < 2; k++) {
            int idx = tid + k*256;
            int dd  = idx >> 5;
            int o4  = idx & 31;
            ((float4*)s_w)[idx] =
                *((const float4*)(W + ((size_t)(g*DD + d0 + dd))*OO + o0) + o4);
        }
        __syncthreads();

        #pragma unroll
        for (int dd = 0; dd < GDT; dd++) {
            float4 w = ((const float4*)s_w)[dd*32 + oq];
            float  m = s_mean[brow*DD + d0 + dd];   // warp-broadcast
            a0 += m*w.x; a1 += m*w.y; a2 += m*w.z; a3 += m*w.w;
        }
    }

    int o = o0 + oq*4;
    float4 bv = *(const float4*)(bias + (size_t)g*OO + o);
    float4 r = make_float4(a0+bv.x, a1+bv.y, a2+bv.z, a3+bv.w);
    *(float4*)(out + ((size_t)((b0 + brow)*GG + g))*OO + o) = r;
}

// ---------------------------------------------------------------- launcher
// metadata order: batch(f32), W(f32), b_bias(f32), token_types(i32),
//                 key_padding_mask(bool -> int32)
extern "C" void kernel_launch(void* const* d_in, const int* in_sizes, int n_in,
                              void* d_out, int out_size) {
    const float* batch = (const float*)d_in[0];
    const float* W     = (const float*)d_in[1];
    const float* bias  = (const float*)d_in[2];
    const int*   tt    = (const int*)d_in[3];
    const int*   pad   = (const int*)d_in[4];
    float* out = (float*)d_out;

    k_setup<<<BB, 256>>>(tt, pad);

    dim3 gmain(TT/CHUNK, BB);
    k_main<<<gmain, 256>>>(batch);

    dim3 ggemm(GG, OO/GOCH, BB/GBH);
    k_gemm<<<ggemm, 256>>>(W, bias, out);
}

// round 4
// speedup vs baseline: 1.7537x; 1.0692x over previous
#include <cuda_runtime.h>

#define BB   32
#define TT   4096
#define DD   512
#define GG   8
#define OO   512
#define CHUNK 128
#define NCHUNK (TT/CHUNK)   // 32

// Scratch (__device__ globals; no allocations allowed)
__device__ float d_sums[BB*GG*DD];
__device__ int   d_counts[BB*GG];
__device__ int   d_st[TT];      // token ids, group-sorted (shared across b)
__device__ int   d_sg[TT];      // group id per sorted slot

// ---------------------------------------------------------------- prep
// grid=32: every CTA zeros one b's sums slice + counts; CTA 0 additionally
// sorts the (batch-independent) token list by group.
__global__ void __launch_bounds__(256) k_prep(const int* __restrict__ tt) {
    int b = blockIdx.x;
    int tid = threadIdx.x;

    // zero this b's sums slice: GG*DD = 4096 floats = 1024 float4
    float4* sz = (float4*)&d_sums[(size_t)b*GG*DD];
    #pragma unroll
    for (int k = 0; k < 4; k++) sz[tid + k*256] = make_float4(0.f,0.f,0.f,0.f);
    if (tid < GG) d_counts[b*GG + tid] = 0;

    if (b != 0) return;

    __shared__ int hist[GG];
    __shared__ int cur[GG];
    if (tid < GG) hist[tid] = 0;
    __syncthreads();
    for (int t = tid; t < TT; t += 256)
        atomicAdd(&hist[tt[t]], 1);
    __syncthreads();
    if (tid == 0) {
        int s = 0;
        for (int g = 0; g < GG; g++) { cur[g] = s; s += hist[g]; }
    }
    __syncthreads();
    for (int t = tid; t < TT; t += 256) {
        int g = tt[t];
        int pos = atomicAdd(&cur[g], 1);
        d_st[pos] = t;
        d_sg[pos] = g;
    }
}

// ------------------------------------------------------------- masked sums
// grid (NCHUNK, BB), 256 threads. lane = tid&127 owns one float4 of D=512,
// half = tid>>7 strides tokens by 2 -> 64 tokens per thread, 8 macro-steps.
// Token list is group-sorted and shared across b; validity comes from the
// pad mask staged in smem. Loads are warp-uniform predicated (@!P issues no
// transaction) and front-batched 8-wide. Accumulator flushes to d_sums via
// atomicAdd only at group boundaries (<=7 per chunk).
__device__ __forceinline__ void flush_acc(int b, int g, int lane, float4 a) {
    float* dst = &d_sums[((size_t)b*GG + g)*DD + lane*4];
    atomicAdd(dst+0, a.x); atomicAdd(dst+1, a.y);
    atomicAdd(dst+2, a.z); atomicAdd(dst+3, a.w);
}

__global__ void __launch_bounds__(256) k_main(const float* __restrict__ batch,
                                              const int* __restrict__ pad) {
    __shared__ int s_tok[CHUNK];
    __shared__ int s_grp[CHUNK];
    __shared__ int s_val[CHUNK];

    int b   = blockIdx.y;
    int c0  = blockIdx.x * CHUNK;
    int tid = threadIdx.x;

    if (tid < CHUNK) {
        int t = d_st[c0 + tid];
        s_tok[tid] = t;
        s_grp[tid] = d_sg[c0 + tid];
        s_val[tid] = pad[(size_t)b*TT + t] ? 0 : 1;   // bool -> int32 transport
    }
    __syncthreads();

    // per-(b,g) valid counts: 64 threads, 16 smem reads each
    if (tid < 64) {
        int g = tid >> 3, j = tid & 7;
        int c = 0;
        #pragma unroll
        for (int k = 0; k < 16; k++) {
            int i = j*16 + k;
            c += (s_grp[i] == g) & s_val[i];
        }
        if (c) atomicAdd(&d_counts[b*GG + g], c);
    }

    int lane = tid & 127;
    int half = tid >> 7;
    const float4* bb = (const float4*)(batch + (size_t)b * TT * DD);

    float4 acc = make_float4(0.f,0.f,0.f,0.f);
    int curg = s_grp[0];

    #define PLOAD(V, J)                                                     \
        float4 V = make_float4(0.f,0.f,0.f,0.f);                            \
        if (s_val[i + 2*(J)])                                               \
            V = __ldcs(&bb[(size_t)s_tok[i + 2*(J)] * (DD/4) + lane]);

    #define ACCSTEP(J, V)                                                   \
        { int g_ = s_grp[i + 2*(J)];                                        \
          if (g_ != curg) {                                                 \
              flush_acc(b, curg, lane, acc);                                \
              acc = make_float4(0.f,0.f,0.f,0.f); curg = g_; }              \
          acc.x += (V).x; acc.y += (V).y; acc.z += (V).z; acc.w += (V).w; }

    #pragma unroll
    for (int s = 0; s < 8; s++) {
        int i = half + s*16;
        PLOAD(v0, 0) PLOAD(v1, 1) PLOAD(v2, 2) PLOAD(v3, 3)
        PLOAD(v4, 4) PLOAD(v5, 5) PLOAD(v6, 6) PLOAD(v7, 7)
        ACCSTEP(0, v0); ACCSTEP(1, v1); ACCSTEP(2, v2); ACCSTEP(3, v3);
        ACCSTEP(4, v4); ACCSTEP(5, v5); ACCSTEP(6, v6); ACCSTEP(7, v7);
    }
    flush_acc(b, curg, lane, acc);
    #undef PLOAD
    #undef ACCSTEP
}

// ------------------------------------------------------ means -> GEMM + bias
// grid (G, OO/128, BB/8), 256 threads. Tile: 8 b-rows x 128 outputs.
// Thread = 1 b-row x 4 outputs; mean reads are warp-broadcast.
#define GBH  8
#define GOCH 128
#define GDT  16

__global__ void __launch_bounds__(256) k_gemm(const float* __restrict__ W,
                                              const float* __restrict__ bias,
                                              float* __restrict__ out) {
    __shared__ float s_mean[GBH * DD];      // 16 KB
    __shared__ float s_w[GDT * GOCH];       //  8 KB

    int g   = blockIdx.x;
    int o0  = blockIdx.y * GOCH;
    int b0  = blockIdx.z * GBH;
    int tid = threadIdx.x;

    for (int idx = tid; idx < GBH*DD; idx += 256) {
        int bl = idx >> 9;
        int d  = idx & (DD-1);
        int bg = (b0 + bl)*GG + g;
        int c  = d_counts[bg];
        float s = d_sums[(size_t)bg*DD + d];
        s_mean[bl*DD + d] = (c > 0) ? s / (float)c : 0.0f;
    }

    int oq   = tid & 31;
    int brow = tid >> 5;
    float a0=0.f, a1=0.f, a2=0.f, a3=0.f;

    for (int d0 = 0; d0 < DD; d0 += GDT) {
        __syncthreads();
        #pragma unroll
        for (int k = 0; k < 2; k++) {
            int idx = tid + k*256;
            int dd  = idx >> 5;
            int o4  = idx & 31;
            ((float4*)s_w)[idx] =
                *((const float4*)(W + ((size_t)(g*DD + d0 + dd))*OO + o0) + o4);
        }
        __syncthreads();

        #pragma unroll
        for (int dd = 0; dd < GDT; dd++) {
            float4 w = ((const float4*)s_w)[dd*32 + oq];
            float  m = s_mean[brow*DD + d0 + dd];
            a0 += m*w.x; a1 += m*w.y; a2 += m*w.z; a3 += m*w.w;
        }
    }

    int o = o0 + oq*4;
    float4 bv = *(const float4*)(bias + (size_t)g*OO + o);
    float4 r = make_float4(a0+bv.x, a1+bv.y, a2+bv.z, a3+bv.w);
    *(float4*)(out + ((size_t)((b0 + brow)*GG + g))*OO + o) = r;
}

// ---------------------------------------------------------------- launcher
// metadata order: batch(f32), W(f32), b_bias(f32), token_types(i32),
//                 key_padding_mask(bool -> int32)
extern "C" void kernel_launch(void* const* d_in, const int* in_sizes, int n_in,
                              void* d_out, int out_size) {
    const float* batch = (const float*)d_in[0];
    const float* W     = (const float*)d_in[1];
    const float* bias  = (const float*)d_in[2];
    const int*   tt    = (const int*)d_in[3];
    const int*   pad   = (const int*)d_in[4];
    float* out = (float*)d_out;

    k_prep<<<BB, 256>>>(tt);

    dim3 gmain(NCHUNK, BB);
    k_main<<<gmain, 256>>>(batch, pad);

    dim3 ggemm(GG, OO/GOCH, BB/GBH);
    k_gemm<<<ggemm, 256>>>(W, bias, out);
}